// round 14
// baseline (speedup 1.0000x reference)
#include <cuda_runtime.h>
#include <math.h>

#define NBATCH 8
#define DPIX   147456     // 384*384
#define KB     256
#define BINS   50

// Scratch (device globals; no dynamic allocation allowed)
__device__ __align__(16) float g_A[NBATCH * KB * KB];   // fine 2D histogram (2 MB, memset node)
__device__ __align__(16) float g_GT[KB * BINS];          // GT[j][c]
__device__ __align__(16) float g_GS[KB];                 // GS[i] = sum_b G[b][i] (telescoped)
__device__ __align__(16) float g_Q [NBATCH * KB];        // Q[n][j] = sum_i GS[i]*H[n][i][j]
__device__ __align__(16) float g_hgram[NBATCH * BINS * BINS];
__device__ float g_mx [NBATCH * BINS];   // row marginals
__device__ float g_myS[NBATCH * BINS];   // col marginals
__device__ float g_Spart[NBATCH];        // per-n totals
__device__ unsigned int g_cnt;           // myE arrival counter (self-resetting)

// ---------------- Kernel 1: nearest-cell 2D histogram + GT/GS tables ----------
__device__ __forceinline__ void red1(float* p, float a) {
    asm volatile("red.global.add.f32 [%0], %1;" :: "l"(p), "f"(a) : "memory");
}

__global__ void k_hist(const float* __restrict__ im1, const float* __restrict__ im2) {
    int gid = blockIdx.x * blockDim.x + threadIdx.x;   // one float4 chunk (4 pixels)

    // fold G-table computation into the first BINS*KB threads
    if (gid < BINS * KB) {
        int b = gid / KB, i = gid % KB;
        float x = (i + 0.5f) * (1.0f / KB);
        float c = (b + 0.5f) * 0.02f;
        float d = 10.0f * (x - c);
        float s1 = 1.0f / (1.0f + __expf(-(d + 0.1f)));
        float s2 = 1.0f / (1.0f + __expf(-(d - 0.1f)));
        g_GT[i * BINS + b] = s1 - s2;
        if (b == 0) {   // GS[i] = sum_b G[b][i], telescoped closed form
            float t1 = 1.0f / (1.0f + __expf(-10.0f * x));
            float t2 = 1.0f / (1.0f + __expf(-10.0f * (x - 1.0f)));
            g_GS[i] = t1 - t2;
        }
    }

    const int nchunk = (NBATCH * DPIX) / 4;
    if (gid >= nchunk) return;
    int n = gid / (DPIX / 4);   // 36864 chunks per batch, no straddle
    float4 xv = ((const float4*)im1)[gid];
    float4 yv = ((const float4*)im2)[gid];
    float* base = g_A + (size_t)n * KB * KB;

    float xs[4] = {xv.x, xv.y, xv.z, xv.w};
    float ys[4] = {yv.x, yv.y, yv.z, yv.w};
#pragma unroll
    for (int q = 0; q < 4; q++) {
        int i0 = min(KB - 1, (int)(xs[q] * 256.0f));
        int j0 = min(KB - 1, (int)(ys[q] * 256.0f));
        red1(base + i0 * KB + j0, 1.0f);
    }
}

// ---------------- Kernel 2: fused C+D — hgram rows + mx + Q, no g_P -----------
// grid = 8(n) * 10(bg: 5 b-rows) = 80 blocks, 256 threads (j)
#define PS_STR 260   // padded stride: 260 mod 32 = 4 -> conflict-free across b
__global__ void __launch_bounds__(256) k_stageCD() {
    int n  = blockIdx.x / 10;
    int bg = blockIdx.x % 10;
    int b0 = bg * 5;
    int j  = threadIdx.x;
    int tid = threadIdx.x;

    __shared__ float Gs[64][6];       // cols 0-4: G rows b0..b0+4; col 5: GS
    __shared__ float Ps[5 * PS_STR];  // P rows for this b-group
    __shared__ float hg[256];

    float acc[5] = {0.f, 0.f, 0.f, 0.f, 0.f};
    float accQ = 0.0f;

    const float* A = g_A + (size_t)n * KB * KB + j;

    for (int it = 0; it < KB; it += 64) {
        __syncthreads();
        for (int t = tid; t < 320; t += 256) {
            int ii = t / 5, k = t % 5;
            Gs[ii][k] = g_GT[(it + ii) * BINS + b0 + k];
        }
        if (tid < 64) Gs[tid][5] = g_GS[it + tid];
        __syncthreads();
#pragma unroll 8
        for (int ii = 0; ii < 64; ii++) {
            float h = A[(size_t)(it + ii) * KB];
            acc[0] += h * Gs[ii][0];
            acc[1] += h * Gs[ii][1];
            acc[2] += h * Gs[ii][2];
            acc[3] += h * Gs[ii][3];
            acc[4] += h * Gs[ii][4];
            accQ   += h * Gs[ii][5];
        }
    }
    if (bg == 0) g_Q[(size_t)n * KB + j] = accQ;

    __syncthreads();
#pragma unroll
    for (int k = 0; k < 5; k++) Ps[k * PS_STR + j] = acc[k];
    __syncthreads();

    // phase 2: hgram[b][c] = sum_j Ps[b][j] * GT[j][c]  (250 outputs)
    float s = 0.0f;
    if (tid < 5 * BINS) {
        int b = tid / BINS, c = tid % BINS;
        const float* Pb = Ps + b * PS_STR;
        const float* GTc = g_GT + c;
        float a0 = 0.f, a1 = 0.f, a2 = 0.f, a3 = 0.f;
#pragma unroll 8
        for (int jj = 0; jj < KB; jj += 4) {
            a0 += Pb[jj]     * GTc[(jj)     * BINS];
            a1 += Pb[jj + 1] * GTc[(jj + 1) * BINS];
            a2 += Pb[jj + 2] * GTc[(jj + 2) * BINS];
            a3 += Pb[jj + 3] * GTc[(jj + 3) * BINS];
        }
        s = (a0 + a1) + (a2 + a3);
        g_hgram[(size_t)(n * BINS + b0 + b) * BINS + c] = s;
    }
    hg[tid] = s;
    __syncthreads();

    // row marginals for the 5 rows
    if (tid < 5) {
        const float* h = hg + tid * BINS;
        float m0 = 0.f, m1 = 0.f;
#pragma unroll
        for (int c = 0; c < BINS; c += 2) { m0 += h[c]; m1 += h[c + 1]; }
        g_mx[n * BINS + b0 + tid] = m0 + m1;
    }
}

// ---------------- Kernel 3: my + S + (last block) MI ---------------------------
// grid = 8 (n), 256 threads
__global__ void __launch_bounds__(256) k_myE(float* __restrict__ out) {
    int n = blockIdx.x;
    int tid = threadIdx.x;
    int g = tid >> 6, c = tid & 63;

    __shared__ float Qs[KB];
    __shared__ float part[4][64];
    __shared__ float rows[64];

    Qs[tid] = g_Q[(size_t)n * KB + tid];
    __syncthreads();

    float s = 0.0f;
    if (c < BINS) {
        const float* GTc = g_GT + c;
        int j0 = g * 64;
        float a0 = 0.f, a1 = 0.f, a2 = 0.f, a3 = 0.f;
#pragma unroll
        for (int j = 0; j < 64; j += 4) {
            a0 += Qs[j0 + j]     * GTc[(j0 + j)     * BINS];
            a1 += Qs[j0 + j + 1] * GTc[(j0 + j + 1) * BINS];
            a2 += Qs[j0 + j + 2] * GTc[(j0 + j + 2) * BINS];
            a3 += Qs[j0 + j + 3] * GTc[(j0 + j + 3) * BINS];
        }
        s = (a0 + a1) + (a2 + a3);
    }
    part[g][c] = s;
    __syncthreads();

    if (tid < 64) {
        float t = (part[0][tid] + part[1][tid]) + (part[2][tid] + part[3][tid]);
        if (tid < BINS) g_myS[n * BINS + tid] = t;
        rows[tid] = (tid < BINS) ? t : 0.0f;
    }
    __syncthreads();
    if (tid < 32) {
        float r = rows[tid] + rows[tid + 32];
#pragma unroll
        for (int o = 16; o; o >>= 1) r += __shfl_xor_sync(0xffffffffu, r, o);
        if (tid == 0) g_Spart[n] = r;
    }

    // ---- last-block tail: full MI (8 blocks total -> negligible drain) -------
    __threadfence();
    __shared__ bool isLast;
    if (tid == 0) isLast = (atomicAdd(&g_cnt, 1u) == NBATCH - 1u);
    __syncthreads();
    if (!isLast) return;
    if (tid == 0) g_cnt = 0;   // reset for next graph replay

    __shared__ float mxs[NBATCH * BINS], mys[NBATCH * BINS];
    __shared__ float red[256];
    __shared__ float sS;
    for (int t = tid; t < NBATCH * BINS; t += 256) {
        mxs[t] = g_mx [t];
        mys[t] = g_myS[t];
    }
    if (tid == 0) {
        float S = 0.0f;
#pragma unroll
        for (int k = 0; k < NBATCH; k++) S += g_Spart[k];
        sS = S;
    }
    __syncthreads();

    float inv = 1.0f / sS;
    float mi = 0.0f;
    const int TOT = NBATCH * BINS * BINS;    // 20000
    for (int t = tid; t < TOT; t += 256) {
        int bIdx = t / BINS;       // = n*BINS + b
        int cc   = t - bIdx * BINS;
        int n2   = bIdx / BINS;
        float p = g_hgram[t] * inv;
        float q = (mxs[bIdx] * inv) * (mys[n2 * BINS + cc] * inv);
        mi += p * __logf(__fdividef(p + 1e-8f, q + 1e-8f));
    }
    red[tid] = mi;
    __syncthreads();
    for (int o = 128; o; o >>= 1) { if (tid < o) red[tid] += red[tid + o]; __syncthreads(); }
    if (tid == 0) out[0] = red[0];
}

// ---------------- Launch -------------------------------------------------------
extern "C" void kernel_launch(void* const* d_in, const int* in_sizes, int n_in,
                              void* d_out, int out_size) {
    const float* im1 = (const float*)d_in[0];
    const float* im2 = (const float*)d_in[1];

    void* aPtr = nullptr;
    cudaGetSymbolAddress(&aPtr, g_A);
    cudaMemsetAsync(aPtr, 0, sizeof(float) * NBATCH * KB * KB);

    k_hist   <<<(NBATCH * DPIX / 4 + 255) / 256, 256>>>(im1, im2);
    k_stageCD<<<80, 256>>>();
    k_myE    <<<8, 256>>>((float*)d_out);
}

// round 15
// speedup vs baseline: 1.9823x; 1.9823x over previous
#include <cuda_runtime.h>
#include <math.h>

#define NBATCH 8
#define DPIX   147456     // 384*384
#define KB     256
#define BINS   50
#define PSTR   (NBATCH * BINS * KB)   // P partial stride
#define QSTR   (NBATCH * KB)          // Q partial stride

// Scratch (device globals; no dynamic allocation allowed)
__device__ __align__(16) float g_A[NBATCH * KB * KB];    // fine 2D histogram (2 MB, memset node)
__device__ __align__(16) float g_GT[KB * BINS];           // GT[i][b]
__device__ __align__(16) float g_GS[KB];                  // GS[i] = sum_b G[b][i] (telescoped)
__device__ __align__(16) float g_P [4 * PSTR];            // P partials [is][n][b][j]
__device__ __align__(16) float g_Q [4 * QSTR];            // Q partials [is][n][j]
__device__ __align__(16) float g_myS[NBATCH * BINS];      // col marginals
__device__ __align__(16) float g_Spart[NBATCH];           // per-n totals

// ---------------- Kernel 1: nearest-cell 2D histogram + GT/GS + out zero ------
__device__ __forceinline__ void red1(float* p, float a) {
    asm volatile("red.global.add.f32 [%0], %1;" :: "l"(p), "f"(a) : "memory");
}

__global__ void k_hist(const float* __restrict__ im1, const float* __restrict__ im2,
                       float* __restrict__ out) {
    int gid = blockIdx.x * blockDim.x + threadIdx.x;   // one float4 chunk (4 pixels)

    if (gid == 0) out[0] = 0.0f;                       // harness poisons d_out

    if (gid < BINS * KB) {
        int b = gid / KB, i = gid % KB;
        float x = (i + 0.5f) * (1.0f / KB);
        float c = (b + 0.5f) * 0.02f;
        float d = 10.0f * (x - c);
        float s1 = 1.0f / (1.0f + __expf(-(d + 0.1f)));
        float s2 = 1.0f / (1.0f + __expf(-(d - 0.1f)));
        g_GT[i * BINS + b] = s1 - s2;
        if (b == 0) {   // GS[i] = sum_b G[b][i], telescoped closed form
            float t1 = 1.0f / (1.0f + __expf(-10.0f * x));
            float t2 = 1.0f / (1.0f + __expf(-10.0f * (x - 1.0f)));
            g_GS[i] = t1 - t2;
        }
    }

    const int nchunk = (NBATCH * DPIX) / 4;
    if (gid >= nchunk) return;
    int n = gid / (DPIX / 4);   // 36864 chunks per batch, no straddle
    float4 xv = ((const float4*)im1)[gid];
    float4 yv = ((const float4*)im2)[gid];
    float* base = g_A + (size_t)n * KB * KB;

    float xs[4] = {xv.x, xv.y, xv.z, xv.w};
    float ys[4] = {yv.x, yv.y, yv.z, yv.w};
#pragma unroll
    for (int q = 0; q < 4; q++) {
        int i0 = min(KB - 1, (int)(xs[q] * 256.0f));
        int j0 = min(KB - 1, (int)(ys[q] * 256.0f));
        red1(base + i0 * KB + j0, 1.0f);
    }
}

// ---------------- Kernel 2: P[is][n][b][j] (+ Q row), 4-way i-split -----------
// grid = 8(n) * 2(jt) * 5(bg: 10 b) * 4(is: 64 i) = 320 blocks, 128 threads
__global__ void __launch_bounds__(128) k_stageC() {
    int blk = blockIdx.x;
    int n  = blk / 40;
    int r  = blk % 40;
    int jt = r / 20;
    int r2 = r % 20;
    int bg = r2 / 4, is = r2 % 4;
    int j  = jt * 128 + threadIdx.x;
    int b0 = bg * 10;
    int it = is * 64;

    __shared__ float Gs[64][12];   // cols 0-9: G rows; col 10: GS; col 11 pad
    float acc[10];
#pragma unroll
    for (int k = 0; k < 10; k++) acc[k] = 0.0f;
    float accQ = 0.0f;

    const float* A = g_A + (size_t)n * KB * KB + j;

    for (int t = threadIdx.x; t < 640; t += 128) {
        int ii = t / 10, k = t % 10;
        Gs[ii][k] = g_GT[(it + ii) * BINS + b0 + k];
    }
    if (threadIdx.x < 64) Gs[threadIdx.x][10] = g_GS[it + threadIdx.x];
    __syncthreads();
#pragma unroll 8
    for (int ii = 0; ii < 64; ii++) {
        float h = A[(size_t)(it + ii) * KB];
        float4 ga = *(const float4*)&Gs[ii][0];
        float4 gb = *(const float4*)&Gs[ii][4];
        float2 gc = *(const float2*)&Gs[ii][8];
        acc[0] += h * ga.x; acc[1] += h * ga.y; acc[2] += h * ga.z; acc[3] += h * ga.w;
        acc[4] += h * gb.x; acc[5] += h * gb.y; acc[6] += h * gb.z; acc[7] += h * gb.w;
        acc[8] += h * gc.x; acc[9] += h * gc.y;
        accQ   += h * Gs[ii][10];
    }

    size_t pb = (size_t)is * PSTR + ((size_t)(n * BINS + b0)) * KB + j;
#pragma unroll
    for (int k = 0; k < 10; k++) g_P[pb + (size_t)k * KB] = acc[k];
    if (bg == 0) g_Q[(size_t)is * QSTR + (size_t)n * KB + j] = accQ;
}

// ---------------- Kernel 3: my[n][c] + Spart[n] --------------------------------
// grid = 8 (n), 256 threads: tid = g*64 + c
__global__ void __launch_bounds__(256) k_my() {
    int n = blockIdx.x;
    __shared__ float Qs[KB];
    __shared__ float part[4][64];
    __shared__ float rows[64];
    int tid = threadIdx.x;
    int g = tid >> 6, c = tid & 63;

    Qs[tid] = g_Q[(size_t)n * KB + tid]
            + g_Q[(size_t)QSTR     + n * KB + tid]
            + g_Q[(size_t)QSTR * 2 + n * KB + tid]
            + g_Q[(size_t)QSTR * 3 + n * KB + tid];
    __syncthreads();

    float s = 0.0f;
    if (c < BINS) {
        const float* GTc = g_GT + c;
        int j0 = g * 64;
        float a0 = 0.f, a1 = 0.f, a2 = 0.f, a3 = 0.f;
#pragma unroll
        for (int j = 0; j < 64; j += 4) {
            a0 += Qs[j0 + j]     * GTc[(j0 + j)     * BINS];
            a1 += Qs[j0 + j + 1] * GTc[(j0 + j + 1) * BINS];
            a2 += Qs[j0 + j + 2] * GTc[(j0 + j + 2) * BINS];
            a3 += Qs[j0 + j + 3] * GTc[(j0 + j + 3) * BINS];
        }
        s = (a0 + a1) + (a2 + a3);
    }
    part[g][c] = s;
    __syncthreads();

    if (tid < 64) {
        float t = (part[0][tid] + part[1][tid]) + (part[2][tid] + part[3][tid]);
        if (tid < BINS) g_myS[n * BINS + tid] = t;
        rows[tid] = (tid < BINS) ? t : 0.0f;
    }
    __syncthreads();
    if (tid < 32) {
        float r = rows[tid] + rows[tid + 32];
#pragma unroll
        for (int o = 16; o; o >>= 1) r += __shfl_xor_sync(0xffffffffu, r, o);
        if (tid == 0) g_Spart[n] = r;
    }
}

// ---------------- Kernel 4: hgram rows + mx + MI terms (fused) -----------------
// grid = 400 (nb = n*50+b), 512 threads: tid = g*64 + c, g in 0..7 (32-j dots)
__global__ void __launch_bounds__(512) k_stageD(float* __restrict__ out) {
    int nb = blockIdx.x;
    int n  = nb / BINS;
    __shared__ float Ps[KB];
    __shared__ float part[8][64];
    __shared__ float rows[64];
    __shared__ float mired[64];
    __shared__ float sMx;
    int tid = threadIdx.x;
    int g = tid >> 6, c = tid & 63;

    // grand total (8 broadcast loads, issued early)
    float S = 0.0f;
#pragma unroll
    for (int k = 0; k < NBATCH; k++) S += g_Spart[k];

    if (tid < KB) {
        size_t base = (size_t)nb * KB + tid;
        Ps[tid] = g_P[base] + g_P[PSTR + base] + g_P[2 * (size_t)PSTR + base]
                + g_P[3 * (size_t)PSTR + base];
    }
    __syncthreads();

    float s = 0.0f;
    if (c < BINS) {
        const float* GTc = g_GT + c;
        int j0 = g * 32;
        float a0 = 0.f, a1 = 0.f, a2 = 0.f, a3 = 0.f;
#pragma unroll
        for (int j = 0; j < 32; j += 4) {
            a0 += Ps[j0 + j]     * GTc[(j0 + j)     * BINS];
            a1 += Ps[j0 + j + 1] * GTc[(j0 + j + 1) * BINS];
            a2 += Ps[j0 + j + 2] * GTc[(j0 + j + 2) * BINS];
            a3 += Ps[j0 + j + 3] * GTc[(j0 + j + 3) * BINS];
        }
        s = (a0 + a1) + (a2 + a3);
    }
    part[g][c] = s;
    __syncthreads();

    float t = 0.0f;
    if (tid < 64) {
        t = ((part[0][tid] + part[1][tid]) + (part[2][tid] + part[3][tid]))
          + ((part[4][tid] + part[5][tid]) + (part[6][tid] + part[7][tid]));
        rows[tid] = (tid < BINS) ? t : 0.0f;
    }
    __syncthreads();
    if (tid < 32) {
        float r = rows[tid] + rows[tid + 32];
#pragma unroll
        for (int o = 16; o; o >>= 1) r += __shfl_xor_sync(0xffffffffu, r, o);
        if (tid == 0) sMx = r;
    }
    __syncthreads();

    // MI terms for this row
    float mi = 0.0f;
    if (tid < BINS) {
        float inv = 1.0f / S;
        float p = t * inv;
        float q = (sMx * inv) * (g_myS[n * BINS + tid] * inv);
        mi = p * __logf(__fdividef(p + 1e-8f, q + 1e-8f));
    }
    if (tid < 64) mired[tid] = mi;
    __syncthreads();
    if (tid < 32) {
        float m = mired[tid] + mired[tid + 32];
#pragma unroll
        for (int o = 16; o; o >>= 1) m += __shfl_xor_sync(0xffffffffu, m, o);
        if (tid == 0) atomicAdd(out, m);
    }
}

// ---------------- Launch -------------------------------------------------------
extern "C" void kernel_launch(void* const* d_in, const int* in_sizes, int n_in,
                              void* d_out, int out_size) {
    const float* im1 = (const float*)d_in[0];
    const float* im2 = (const float*)d_in[1];

    void* aPtr = nullptr;
    cudaGetSymbolAddress(&aPtr, g_A);
    cudaMemsetAsync(aPtr, 0, sizeof(float) * NBATCH * KB * KB);

    k_hist  <<<(NBATCH * DPIX / 4 + 255) / 256, 256>>>(im1, im2, (float*)d_out);
    k_stageC<<<320, 128>>>();
    k_my    <<<8, 256>>>();
    k_stageD<<<400, 512>>>((float*)d_out);
}